// round 5
// baseline (speedup 1.0000x reference)
#include <cuda_runtime.h>
#include <math.h>

// ---------------------------------------------------------------------------
// DepthModule: plane-sweep stereo depth network, fp32.
// Pipeline:
//  A) setup_proj  : per-frame fused projection  proj = d*(K R Kinv)pix + K t
//  T) transpose wd1 -> [ic][k27][oc] for vectorized weight loads
//  B) conv1 (3->32, s2)   images -> g_f1 (5,32,240,320)
//  C) conv2 (32->32, s2)  g_f1 -> g_f2 (5,32,120,160)
//  C) conv3 (32->32, s2)  g_f2 -> g_f3 (5,32,60,80)   == fmaps
//  D) build_volume: warped-average half of cost volume (32 ch) only
//  E0) refconv    : ref half of conv3d collapsed to 3 x 2D convs (per kd slice)
//  E) conv3d_main : 32ic x 27tap x 32oc over avg channels + ref init, relu
//  F1) logits     : 32->1 conv3d
//  F2) softmax over depth + expectation -> out (60x80)
// ---------------------------------------------------------------------------

#define N_F1 (5*32*240*320)
#define N_F2 (5*32*120*160)
#define N_F3 (5*32*60*80)
#define N_VOX (32*60*80)          // 153600

__device__ float g_prm[64];                       // 5 frames x (M 3x3, b 3)
__device__ __align__(16) float g_f1[N_F1];
__device__ __align__(16) float g_f2[N_F2];
__device__ __align__(16) float g_f3[N_F3];
__device__ __align__(16) float g_vol[32*N_VOX];   // avg channels only
__device__ __align__(16) float g_wt1t[64*27*32];  // wd1 transposed [ic][k][oc]
__device__ __align__(16) float g_sref[3*32*4800]; // [kd-slice][oc][y*80+x]
__device__ __align__(16) float g_h3[32*N_VOX];
__device__ __align__(16) float g_logits[N_VOX];

// --------------------------------------------------------------------------
__global__ void setup_proj_kernel(const float* __restrict__ poses,
                                  const float* __restrict__ intr)
{
    if (threadIdx.x != 0) return;
    // Gauss-Jordan inverse of poses[0] (4x4)
    float A[4][8];
    for (int r = 0; r < 4; r++)
        for (int c = 0; c < 4; c++) {
            A[r][c]   = poses[r*4 + c];
            A[r][4+c] = (r == c) ? 1.f : 0.f;
        }
    for (int col = 0; col < 4; col++) {
        int piv = col; float best = fabsf(A[col][col]);
        for (int r = col+1; r < 4; r++) {
            float v = fabsf(A[r][col]);
            if (v > best) { best = v; piv = r; }
        }
        if (piv != col)
            for (int c = 0; c < 8; c++) {
                float t = A[col][c]; A[col][c] = A[piv][c]; A[piv][c] = t;
            }
        float inv = 1.f / A[col][col];
        for (int c = 0; c < 8; c++) A[col][c] *= inv;
        for (int r = 0; r < 4; r++) {
            if (r == col) continue;
            float fv = A[r][col];
            for (int c = 0; c < 8; c++) A[r][c] -= fv * A[col][c];
        }
    }
    float fx = intr[0]*0.25f, fy = intr[1]*0.25f;
    float cx = intr[2]*0.25f, cy = intr[3]*0.25f;
    float ifx = 1.f/fx, ify = 1.f/fy;
    for (int f = 0; f < 5; f++) {
        const float* P = poses + f*16;
        float G[3][4];
        for (int r = 0; r < 3; r++)
            for (int c = 0; c < 4; c++) {
                float s = 0.f;
                for (int k = 0; k < 4; k++) s += P[r*4+k] * A[k][4+c];
                G[r][c] = s;
            }
        float KR[3][4];
        for (int c = 0; c < 4; c++) {
            KR[0][c] = fx*G[0][c] + cx*G[2][c];
            KR[1][c] = fy*G[1][c] + cy*G[2][c];
            KR[2][c] = G[2][c];
        }
        for (int r = 0; r < 3; r++) {
            g_prm[f*12 + r*3 + 0] = KR[r][0]*ifx;
            g_prm[f*12 + r*3 + 1] = KR[r][1]*ify;
            g_prm[f*12 + r*3 + 2] = -KR[r][0]*cx*ifx - KR[r][1]*cy*ify + KR[r][2];
            g_prm[f*12 + 9 + r]   = KR[r][3];
        }
    }
}

// --------------------------------------------------------------------------
__global__ void transpose_wd1_kernel(const float* __restrict__ wd1)
{
    int i = blockIdx.x*blockDim.x + threadIdx.x;
    if (i >= 55296) return;
    int oc = i / 1728;          // 64*27
    int r  = i % 1728;
    int ic = r / 27, kk = r % 27;
    g_wt1t[(ic*27 + kk)*32 + oc] = wd1[i];
}

// --------------------------------------------------------------------------
// conv1: 3->32, stride 2, SAME (pad lo=0, hi=1), input normalized on the fly
__global__ void conv1_kernel(const float* __restrict__ img,
                             const float* __restrict__ w1,
                             const float* __restrict__ b1)
{
    __shared__ __align__(16) float ws[864];       // [(ic*9+k)*32 + oc]
    for (int i = threadIdx.x; i < 864; i += blockDim.x) {
        int oc = i / 27, r = i % 27;
        ws[r*32 + oc] = w1[i];
    }
    __syncthreads();
    int idx = blockIdx.x*blockDim.x + threadIdx.x;
    if (idx >= 5*240*320) return;
    int x = idx % 320, y = (idx/320) % 240, f = idx/(320*240);
    float acc[32];
    #pragma unroll
    for (int o = 0; o < 32; o++) acc[o] = 0.f;
    const float* ip = img + f*3*480*640;
    #pragma unroll
    for (int ic = 0; ic < 3; ic++) {
        float v[9];
        #pragma unroll
        for (int ky = 0; ky < 3; ky++) {
            int iy = 2*y + ky;
            #pragma unroll
            for (int kx = 0; kx < 3; kx++) {
                int ix = 2*x + kx;
                v[ky*3+kx] = (iy < 480 && ix < 640)
                    ? fmaf(__ldg(ip + (ic*480 + iy)*640 + ix), 2.f/255.f, -1.f)
                    : 0.f;
            }
        }
        const float4* wp = (const float4*)(ws + ic*288);
        #pragma unroll
        for (int k = 0; k < 9; k++) {
            float vk = v[k];
            #pragma unroll
            for (int o4 = 0; o4 < 8; o4++) {
                float4 w = wp[k*8 + o4];
                acc[o4*4+0] = fmaf(w.x, vk, acc[o4*4+0]);
                acc[o4*4+1] = fmaf(w.y, vk, acc[o4*4+1]);
                acc[o4*4+2] = fmaf(w.z, vk, acc[o4*4+2]);
                acc[o4*4+3] = fmaf(w.w, vk, acc[o4*4+3]);
            }
        }
    }
    float* op = g_f1 + f*32*240*320 + y*320 + x;
    #pragma unroll
    for (int o = 0; o < 32; o++)
        op[o*240*320] = fmaxf(acc[o] + __ldg(b1 + o), 0.f);
}

// --------------------------------------------------------------------------
// conv2/conv3: 32->32, stride 2, SAME (pad lo=0, hi=1). stage 0: f1->f2; 1: f2->f3
__global__ void conv2s_kernel(int stage, const float* __restrict__ w,
                              const float* __restrict__ b)
{
    __shared__ __align__(16) float ws[9216];      // [(ic*9+k)*32 + oc]
    for (int i = threadIdx.x; i < 9216; i += blockDim.x) {
        int oc = i / 288, r = i % 288;
        ws[r*32 + oc] = w[i];
    }
    __syncthreads();
    const float* in = (stage == 0) ? g_f1 : g_f2;
    float* out      = (stage == 0) ? g_f2 : g_f3;
    int inH = (stage == 0) ? 240 : 120;
    int inW = (stage == 0) ? 320 : 160;
    int outH = inH >> 1, outW = inW >> 1;
    int idx = blockIdx.x*blockDim.x + threadIdx.x;
    int total = 5*outH*outW;
    if (idx >= total) return;
    int x = idx % outW, y = (idx/outW) % outH, f = idx/(outW*outH);
    float acc[32];
    #pragma unroll
    for (int o = 0; o < 32; o++) acc[o] = 0.f;
    const float* ip = in + f*32*inH*inW;
    for (int ic = 0; ic < 32; ic++) {
        float v[9];
        #pragma unroll
        for (int ky = 0; ky < 3; ky++) {
            int iy = 2*y + ky;
            #pragma unroll
            for (int kx = 0; kx < 3; kx++) {
                int ix = 2*x + kx;
                v[ky*3+kx] = (iy < inH && ix < inW)
                    ? __ldg(ip + (ic*inH + iy)*inW + ix) : 0.f;
            }
        }
        const float4* wp = (const float4*)(ws + ic*288);
        #pragma unroll
        for (int k = 0; k < 9; k++) {
            float vk = v[k];
            #pragma unroll
            for (int o4 = 0; o4 < 8; o4++) {
                float4 wv = wp[k*8 + o4];
                acc[o4*4+0] = fmaf(wv.x, vk, acc[o4*4+0]);
                acc[o4*4+1] = fmaf(wv.y, vk, acc[o4*4+1]);
                acc[o4*4+2] = fmaf(wv.z, vk, acc[o4*4+2]);
                acc[o4*4+3] = fmaf(wv.w, vk, acc[o4*4+3]);
            }
        }
    }
    float* op = out + f*32*outH*outW + y*outW + x;
    #pragma unroll
    for (int o = 0; o < 32; o++)
        op[o*outH*outW] = fmaxf(acc[o] + __ldg(b + o), 0.f);
}

// --------------------------------------------------------------------------
// Cost volume, warped-average channels only (mean over 5 frames, bilinear)
__global__ void build_volume_kernel()
{
    int idx = blockIdx.x*blockDim.x + threadIdx.x;
    if (idx >= N_VOX) return;
    int x  = idx % 80;
    int y  = (idx / 80) % 60;
    int dd = idx / 4800;
    float depth = 0.25f + 0.25f*(float)dd;        // linspace(0.25,8,32) exact
    float fxp = (float)x, fyp = (float)y;
    float sum[32];
    #pragma unroll
    for (int c = 0; c < 32; c++) sum[c] = 0.f;
    for (int f = 0; f < 5; f++) {
        const float* P = g_prm + f*12;
        float nu = depth*(P[0]*fxp + P[1]*fyp + P[2]) + P[9];
        float nv = depth*(P[3]*fxp + P[4]*fyp + P[5]) + P[10];
        float z  = depth*(P[6]*fxp + P[7]*fyp + P[8]) + P[11];
        float iz = 1.f/(z + 1e-8f);
        float u = nu*iz, v = nv*iz;
        float x0f = floorf(u), y0f = floorf(v);
        float wx = u - x0f, wy = v - y0f;
        int x0 = (int)x0f, y0 = (int)y0f;
        int xc0 = min(max(x0,   0), 79), xc1 = min(max(x0+1, 0), 79);
        int yc0 = min(max(y0,   0), 59), yc1 = min(max(y0+1, 0), 59);
        float valid = (u >= 0.f && u <= 79.f && v >= 0.f && v <= 59.f) ? 1.f : 0.f;
        float w00 = (1.f-wx)*(1.f-wy)*valid;
        float w10 = wx*(1.f-wy)*valid;
        float w01 = (1.f-wx)*wy*valid;
        float w11 = wx*wy*valid;
        const float* fb = g_f3 + f*32*4800;
        int i00 = yc0*80 + xc0, i01 = yc0*80 + xc1;
        int i10 = yc1*80 + xc0, i11 = yc1*80 + xc1;
        #pragma unroll
        for (int c = 0; c < 32; c++) {
            const float* fc = fb + c*4800;
            sum[c] += w00*__ldg(fc+i00) + w10*__ldg(fc+i01)
                    + w01*__ldg(fc+i10) + w11*__ldg(fc+i11);
        }
    }
    #pragma unroll
    for (int c = 0; c < 32; c++)
        g_vol[c*N_VOX + idx] = sum[c] * 0.2f;
}

// --------------------------------------------------------------------------
// Ref-channel contribution to conv3d, collapsed per kd slice (d-invariant):
// sref[s][oc][p] = sum_{ic<32,ky,kx} wd1[oc][ic][s][ky][kx] * fmap0[ic][p+off]
__global__ void refconv_kernel()
{
    int s = blockIdx.y;                           // kd slice 0..2
    __shared__ __align__(16) float ws[9216];      // [ic][k2][oc]
    for (int i = threadIdx.x; i < 9216; i += blockDim.x) {
        int ic = i / 288, r = i % 288;
        int k2 = r / 32, oc = r % 32;
        ws[i] = g_wt1t[(ic*27 + s*9 + k2)*32 + oc];
    }
    __syncthreads();
    int idx = blockIdx.x*blockDim.x + threadIdx.x;
    if (idx >= 4800) return;
    int x = idx % 80, y = idx / 80;
    float acc[32];
    #pragma unroll
    for (int o = 0; o < 32; o++) acc[o] = 0.f;
    for (int ic = 0; ic < 32; ic++) {
        float v[9];
        #pragma unroll
        for (int ky = 0; ky < 3; ky++) {
            int yy = y + ky - 1;
            #pragma unroll
            for (int kx = 0; kx < 3; kx++) {
                int xx = x + kx - 1;
                v[ky*3+kx] = (yy >= 0 && yy < 60 && xx >= 0 && xx < 80)
                    ? __ldg(g_f3 + ic*4800 + yy*80 + xx) : 0.f;
            }
        }
        const float4* wp = (const float4*)(ws + ic*288);
        #pragma unroll
        for (int k = 0; k < 9; k++) {
            float vk = v[k];
            #pragma unroll
            for (int o4 = 0; o4 < 8; o4++) {
                float4 wv = wp[k*8 + o4];
                acc[o4*4+0] = fmaf(wv.x, vk, acc[o4*4+0]);
                acc[o4*4+1] = fmaf(wv.y, vk, acc[o4*4+1]);
                acc[o4*4+2] = fmaf(wv.z, vk, acc[o4*4+2]);
                acc[o4*4+3] = fmaf(wv.w, vk, acc[o4*4+3]);
            }
        }
    }
    #pragma unroll
    for (int o = 0; o < 32; o++)
        g_sref[(s*32 + o)*4800 + idx] = acc[o];
}

// --------------------------------------------------------------------------
// Main conv3d: avg channels (wd1 ic 32..63), init from sref + bias, relu.
// Register tile: 8 oc x 4 x-voxels per thread. block (20,4,3), grid (32,20).
__global__ void conv3d_main_kernel(const float* __restrict__ bd1)
{
    int tx = threadIdx.x;           // x group (4 voxels)
    int ty = threadIdx.y;           // oc group (8 oc)
    int tz = threadIdx.z;           // y row
    int d  = blockIdx.x;
    int y  = blockIdx.y*3 + tz;
    int x0 = tx*4;
    int oc0 = ty*8;

    float acc[8][4];
    #pragma unroll
    for (int o = 0; o < 8; o++) {
        float bias = __ldg(bd1 + oc0 + o);
        #pragma unroll
        for (int xv = 0; xv < 4; xv++) {
            int p = y*80 + x0 + xv;
            float a = bias + g_sref[(32 + oc0 + o)*4800 + p];   // kd=1 always
            if (d >= 1)  a += g_sref[(oc0 + o)*4800 + p];       // kd=0
            if (d <= 30) a += g_sref[(64 + oc0 + o)*4800 + p];  // kd=2
            acc[o][xv] = a;
        }
    }

    for (int ic = 0; ic < 32; ic++) {
        const float* ip = g_vol + ic*N_VOX;
        #pragma unroll
        for (int kd = 0; kd < 3; kd++) {
            int dz = d + kd - 1;
            if (dz < 0 || dz > 31) continue;
            #pragma unroll
            for (int ky = 0; ky < 3; ky++) {
                int yy = y + ky - 1;
                if (yy < 0 || yy > 59) continue;
                const float* rp = ip + (dz*60 + yy)*80;
                float v[6];
                #pragma unroll
                for (int j = 0; j < 6; j++) {
                    int xx = x0 - 1 + j;
                    v[j] = (xx >= 0 && xx < 80) ? __ldg(rp + xx) : 0.f;
                }
                #pragma unroll
                for (int kx = 0; kx < 3; kx++) {
                    const float4* wp = (const float4*)
                        (g_wt1t + ((32+ic)*27 + kd*9 + ky*3 + kx)*32 + oc0);
                    float4 wa = __ldg(wp), wb = __ldg(wp+1);
                    float w8[8] = {wa.x, wa.y, wa.z, wa.w, wb.x, wb.y, wb.z, wb.w};
                    #pragma unroll
                    for (int o = 0; o < 8; o++)
                        #pragma unroll
                        for (int xv = 0; xv < 4; xv++)
                            acc[o][xv] = fmaf(w8[o], v[kx+xv], acc[o][xv]);
                }
            }
        }
    }

    #pragma unroll
    for (int o = 0; o < 8; o++) {
        float4 r;
        r.x = fmaxf(acc[o][0], 0.f);
        r.y = fmaxf(acc[o][1], 0.f);
        r.z = fmaxf(acc[o][2], 0.f);
        r.w = fmaxf(acc[o][3], 0.f);
        *(float4*)(g_h3 + (oc0+o)*N_VOX + d*4800 + y*80 + x0) = r;
    }
}

// --------------------------------------------------------------------------
__global__ void logits_kernel(const float* __restrict__ wd2,
                              const float* __restrict__ bd2)
{
    __shared__ float ws[864];
    for (int i = threadIdx.x; i < 864; i += blockDim.x) ws[i] = wd2[i];
    __syncthreads();
    int idx = blockIdx.x*blockDim.x + threadIdx.x;
    if (idx >= N_VOX) return;
    int x = idx % 80, y = (idx/80) % 60, d = idx/4800;
    float acc = __ldg(bd2);
    for (int ic = 0; ic < 32; ic++) {
        const float* ip = g_h3 + ic*N_VOX;
        const float* wp = ws + ic*27;
        #pragma unroll
        for (int kd = 0; kd < 3; kd++) {
            int dz = d + kd - 1;
            if (dz < 0 || dz > 31) continue;
            #pragma unroll
            for (int ky = 0; ky < 3; ky++) {
                int yy = y + ky - 1;
                if (yy < 0 || yy > 59) continue;
                const float* rp = ip + (dz*60 + yy)*80;
                #pragma unroll
                for (int kx = 0; kx < 3; kx++) {
                    int xx = x + kx - 1;
                    if (xx < 0 || xx > 79) continue;
                    acc = fmaf(wp[kd*9 + ky*3 + kx], __ldg(rp + xx), acc);
                }
            }
        }
    }
    g_logits[idx] = acc;
}

// --------------------------------------------------------------------------
__global__ void depth_out_kernel(float* __restrict__ out)
{
    int idx = blockIdx.x*blockDim.x + threadIdx.x;
    if (idx >= 4800) return;
    float l[32];
    float m = -1e30f;
    #pragma unroll
    for (int d = 0; d < 32; d++) {
        l[d] = g_logits[d*4800 + idx];
        m = fmaxf(m, l[d]);
    }
    float s = 0.f, num = 0.f;
    #pragma unroll
    for (int d = 0; d < 32; d++) {
        float e = expf(l[d] - m);
        s += e;
        num += (0.25f + 0.25f*(float)d) * e;
    }
    out[idx] = num / s;
}

// --------------------------------------------------------------------------
extern "C" void kernel_launch(void* const* d_in, const int* in_sizes, int n_in,
                              void* d_out, int out_size)
{
    const float* poses  = (const float*)d_in[0];
    const float* images = (const float*)d_in[1];
    const float* intr   = (const float*)d_in[2];
    const float* w1  = (const float*)d_in[3];
    const float* b1  = (const float*)d_in[4];
    const float* w2  = (const float*)d_in[5];
    const float* b2  = (const float*)d_in[6];
    const float* w3  = (const float*)d_in[7];
    const float* b3  = (const float*)d_in[8];
    const float* wd1 = (const float*)d_in[9];
    const float* bd1 = (const float*)d_in[10];
    const float* wd2 = (const float*)d_in[11];
    const float* bd2 = (const float*)d_in[12];
    float* out = (float*)d_out;

    setup_proj_kernel<<<1, 32>>>(poses, intr);
    transpose_wd1_kernel<<<216, 256>>>(wd1);
    conv1_kernel<<<1500, 256>>>(images, w1, b1);        // 5*240*320 threads
    conv2s_kernel<<<375, 256>>>(0, w2, b2);             // 5*120*160
    conv2s_kernel<<<94, 256>>>(1, w3, b3);              // 5*60*80
    build_volume_kernel<<<600, 256>>>();                // 153600
    refconv_kernel<<<dim3(38, 3), 128>>>();             // 4800 x 3 slices
    conv3d_main_kernel<<<dim3(32, 20), dim3(20, 4, 3)>>>(bd1);
    logits_kernel<<<600, 256>>>(wd2, bd2);              // 153600
    depth_out_kernel<<<19, 256>>>(out);                 // 4800
}